// round 3
// baseline (speedup 1.0000x reference)
#include <cuda_runtime.h>
#include <cuda_bf16.h>
#include <math.h>

// Problem dims
#define Bn 512
#define Tn 512
#define In 256
#define Hn 250

// ---------------- scratch: padded Wh [250][256] (cols 250..255 = 0) ----------
__device__ float g_WhP[Hn * 256];

__global__ void prep_whp_kernel(const float* __restrict__ Wh) {
    int i = blockIdx.x * blockDim.x + threadIdx.x;   // 250*256 threads exactly
    int r = i >> 8;
    int k = i & 255;
    g_WhP[i] = (k < Hn) ? Wh[r * Hn + k] : 0.0f;
}

// ---------------- Phase 1: xproj GEMM  out[m, j] = sum_i x[m,i] * Wx[j,i] ----
// M = B*T = 262144, K = 256, N = 250. Written in-place into d_out [B,T,H].
#define BM 128
#define BN 128
#define BK 16
#define TM 8
#define TN 8
#define GEMM_THREADS 256
#define SPAD 132   // smem row stride (padded)

__global__ __launch_bounds__(GEMM_THREADS)
void gemm_xproj_kernel(const float* __restrict__ X,
                       const float* __restrict__ Wx,
                       float* __restrict__ out) {
    __shared__ float As[BK][SPAD];
    __shared__ float Bs[BK][SPAD];

    const int t  = threadIdx.x;
    const int m0 = blockIdx.x * BM;
    const int j0 = blockIdx.y * BN;

    const int tx = t & 15;   // 0..15  -> N direction
    const int ty = t >> 4;   // 0..15  -> M direction

    const int lr = t >> 2;   // 0..63 load row
    const int lc = t & 3;    // 0..3  float4 col within 16-wide k tile

    float acc[TM][TN];
    #pragma unroll
    for (int i = 0; i < TM; i++)
        #pragma unroll
        for (int jj = 0; jj < TN; jj++)
            acc[i][jj] = 0.0f;

    for (int k0 = 0; k0 < In; k0 += BK) {
        // load A tile (128 rows x 16 k), store transposed As[k][m]
        #pragma unroll
        for (int rr = 0; rr < 2; rr++) {
            int m = lr + rr * 64;
            float4 v = *(const float4*)(X + (size_t)(m0 + m) * In + k0 + lc * 4);
            As[lc * 4 + 0][m] = v.x;
            As[lc * 4 + 1][m] = v.y;
            As[lc * 4 + 2][m] = v.z;
            As[lc * 4 + 3][m] = v.w;
        }
        // load B tile: Bs[k][j] = Wx[j0+j][k0+k], zero-fill j >= 250
        #pragma unroll
        for (int rr = 0; rr < 2; rr++) {
            int jj = lr + rr * 64;
            int gj = j0 + jj;
            float4 v = make_float4(0.f, 0.f, 0.f, 0.f);
            if (gj < Hn)
                v = *(const float4*)(Wx + (size_t)gj * In + k0 + lc * 4);
            Bs[lc * 4 + 0][jj] = v.x;
            Bs[lc * 4 + 1][jj] = v.y;
            Bs[lc * 4 + 2][jj] = v.z;
            Bs[lc * 4 + 3][jj] = v.w;
        }
        __syncthreads();

        #pragma unroll
        for (int kk = 0; kk < BK; kk++) {
            float a[TM], b[TN];
            float4 a0 = *(const float4*)(&As[kk][ty * TM + 0]);
            float4 a1 = *(const float4*)(&As[kk][ty * TM + 4]);
            float4 b0 = *(const float4*)(&Bs[kk][tx * TN + 0]);
            float4 b1 = *(const float4*)(&Bs[kk][tx * TN + 4]);
            a[0]=a0.x; a[1]=a0.y; a[2]=a0.z; a[3]=a0.w;
            a[4]=a1.x; a[5]=a1.y; a[6]=a1.z; a[7]=a1.w;
            b[0]=b0.x; b[1]=b0.y; b[2]=b0.z; b[3]=b0.w;
            b[4]=b1.x; b[5]=b1.y; b[6]=b1.z; b[7]=b1.w;
            #pragma unroll
            for (int i = 0; i < TM; i++)
                #pragma unroll
                for (int jj = 0; jj < TN; jj++)
                    acc[i][jj] += a[i] * b[jj];
        }
        __syncthreads();
    }

    // epilogue: out row stride = 250
    #pragma unroll
    for (int i = 0; i < TM; i++) {
        int m = m0 + ty * TM + i;
        #pragma unroll
        for (int jj = 0; jj < TN; jj++) {
            int gj = j0 + tx * TN + jj;
            if (gj < Hn)
                out[(size_t)m * Hn + gj] = acc[i][jj];
        }
    }
}

// ---------------- Phase 2: recurrent scan -----------------------------------
// 128 CTAs x 4 batches. Thread j computes h_new[bb][j].
// smem: Wh rows, cols 0..219 (stride 220, conflict-free) + h ping-pong buffers.
// Wh cols 220..255 (padded) live in 9 float4 registers per thread for the
// whole t-loop. xproj is read from (and h written back into) d_out in place.
#define KC 220                      // k columns cached in smem
#define KC4 (KC / 4)                // 55 float4 chunks
#define WREG 9                      // (256 - 220)/4 register chunks
#define HBUF 256                    // padded h row (cols 250..255 stay 0)
#define SCAN_SMEM_BYTES (Hn * KC * 4 + 2 * 4 * HBUF * 4)

__global__ __launch_bounds__(256, 1)
void rnn_scan_kernel(const float* __restrict__ h0,
                     const float* __restrict__ bh,
                     float* out) {
    extern __shared__ float sm[];
    float* WhS = sm;                    // [250][220]
    float* hb  = sm + Hn * KC;          // [2][4][256]

    const int j  = threadIdx.x;         // 0..255
    const int jj = (j < Hn) ? j : (Hn - 1);   // clamp for lanes 250..255
    const int b0 = blockIdx.x * 4;

    // fill smem Wh cache (coalesced-ish one-time load)
    for (int idx = j; idx < Hn * KC; idx += 256) {
        int r = idx / KC;
        int c = idx - r * KC;
        WhS[idx] = g_WhP[r * 256 + c];
    }
    // zero both h buffers (keeps pad cols 250..255 at 0 forever)
    for (int idx = j; idx < 2 * 4 * HBUF; idx += 256)
        hb[idx] = 0.0f;
    __syncthreads();
    // load initial h
    if (j < Hn) {
        #pragma unroll
        for (int bb = 0; bb < 4; bb++)
            hb[0 * (4 * HBUF) + bb * HBUF + j] = h0[(size_t)(b0 + bb) * Hn + j];
    }

    const float bias = bh[jj];

    // register-resident tail of Wh row jj: k = 220..255 (includes zero pad)
    float4 wg[WREG];
    {
        const float4* rowp = (const float4*)(g_WhP + (size_t)jj * 256);
        #pragma unroll
        for (int q = 0; q < WREG; q++)
            wg[q] = rowp[KC4 + q];
    }
    __syncthreads();

    int p = 0;
    for (int t = 0; t < Tn; t++) {
        // prefetch xproj for this step (consumed after the k-loop -> latency hidden)
        float xp[4];
        if (j < Hn) {
            #pragma unroll
            for (int bb = 0; bb < 4; bb++)
                xp[bb] = out[((size_t)(b0 + bb) * Tn + t) * Hn + j];
        } else {
            xp[0] = xp[1] = xp[2] = xp[3] = 0.0f;
        }

        float acc[4];
        #pragma unroll
        for (int bb = 0; bb < 4; bb++) acc[bb] = bias;

        const float4* hbp = (const float4*)(hb + p * (4 * HBUF)); // [4][64] float4

        // smem part: k = 0..219
        const float4* wrow = (const float4*)(WhS + jj * KC);
        #pragma unroll 5
        for (int kc = 0; kc < KC4; kc++) {
            float4 w = wrow[kc];
            #pragma unroll
            for (int bb = 0; bb < 4; bb++) {
                float4 hv = hbp[bb * 64 + kc];
                acc[bb] += w.x * hv.x;
                acc[bb] += w.y * hv.y;
                acc[bb] += w.z * hv.z;
                acc[bb] += w.w * hv.w;
            }
        }
        // register part: k = 220..255 (pad contributes 0)
        #pragma unroll
        for (int q = 0; q < WREG; q++) {
            float4 w = wg[q];
            #pragma unroll
            for (int bb = 0; bb < 4; bb++) {
                float4 hv = hbp[bb * 64 + KC4 + q];
                acc[bb] += w.x * hv.x;
                acc[bb] += w.y * hv.y;
                acc[bb] += w.z * hv.z;
                acc[bb] += w.w * hv.w;
            }
        }

        float* hnx = hb + (1 - p) * (4 * HBUF);
        #pragma unroll
        for (int bb = 0; bb < 4; bb++) {
            float hv = tanhf(acc[bb] + xp[bb]);
            if (j < Hn) {
                hnx[bb * HBUF + j] = hv;
                out[((size_t)(b0 + bb) * Tn + t) * Hn + j] = hv;
            }
        }
        __syncthreads();
        p ^= 1;
    }
}

// ---------------- launch ------------------------------------------------------
extern "C" void kernel_launch(void* const* d_in, const int* in_sizes, int n_in,
                              void* d_out, int out_size) {
    const float* x  = (const float*)d_in[0];   // [512,512,256]
    const float* h0 = (const float*)d_in[1];   // [512,250]
    const float* Wx = (const float*)d_in[2];   // [250,256]
    const float* Wh = (const float*)d_in[3];   // [250,250]
    const float* bh = (const float*)d_in[4];   // [250]
    float* out = (float*)d_out;                // [512,512,250]

    // 1) pad Wh into device scratch
    prep_whp_kernel<<<Hn, 256>>>(Wh);

    // 2) xproj GEMM straight into d_out
    dim3 grid((Bn * Tn) / BM, 2);
    gemm_xproj_kernel<<<grid, GEMM_THREADS>>>(x, Wx, out);

    // 3) recurrent scan (in-place over d_out)
    cudaFuncSetAttribute(rnn_scan_kernel,
                         cudaFuncAttributeMaxDynamicSharedMemorySize,
                         SCAN_SMEM_BYTES);
    rnn_scan_kernel<<<(Bn / 4), 256, SCAN_SMEM_BYTES>>>(h0, bh, out);
}